// round 1
// baseline (speedup 1.0000x reference)
#include <cuda_runtime.h>
#include <math.h>

#define NRAYS 65536
#define NT0   128
#define NT1   64
#define NCH   16

// global scalar accumulators: [0]=prop_sum, [1]=uni_sum, [2]=bi_sum
__device__ double g_acc[3];

__device__ __forceinline__ float n2n(float v) {
    if (isnan(v)) return 0.f;
    if (isinf(v)) return v > 0.f ? 3.4028234663852886e38f : -3.4028234663852886e38f;
    return v;
}
__device__ __forceinline__ float spacing_fn(float x)  { return x < 1.f  ? 0.5f * x : 1.f - 1.f / (2.f * x); }
__device__ __forceinline__ float spacing_inv(float x) { return x < 0.5f ? 2.f * x  : 1.f / (2.f - 2.f * x); }

__device__ __forceinline__ float warp_incl_scan(float v, int lane) {
#pragma unroll
    for (int o = 1; o < 32; o <<= 1) {
        float y = __shfl_up_sync(0xffffffffu, v, o);
        if (lane >= o) v += y;
    }
    return v;
}
__device__ __forceinline__ float warp_red(float v) {
#pragma unroll
    for (int o = 16; o; o >>= 1) v += __shfl_xor_sync(0xffffffffu, v, o);
    return v;
}

__device__ __forceinline__ void contract_pt(float& x, float& y, float& z) {
    float ax = fabsf(x), ay = fabsf(y), az = fabsf(z);
    float mag = fmaxf(ax, fmaxf(ay, az));
    if (mag < 1.f) return;  // NaN mag falls through (matches jnp.where semantics)
    int idx = (ax >= ay && ax >= az) ? 0 : ((ay >= az) ? 1 : 2);
    float inv = 1.f / mag;
    float s = (2.f - inv) * inv;
    x *= (idx == 0) ? s : inv;
    y *= (idx == 1) ? s : inv;
    z *= (idx == 2) ? s : inv;
}

__global__ void init_k() { if (threadIdx.x < 3) g_acc[threadIdx.x] = 0.0; }

__global__ void final_k(float* out) {
    const double Nf = (double)NRAYS;
    out[7 * NRAYS]     = (float)(g_acc[0] / (Nf * 64.0));
    out[7 * NRAYS + 1] = (float)(g_acc[1] / (3.0 * Nf) + 2.0 * g_acc[2] / Nf);
}

struct WarpSh {
    float cdf[132];    // 129 used: cdf[0]=0, cdf[1..128]
    float bins1[68];   // 65 used
    float rb1[68];     // 65 used
    float cw0[132];    // 129 used: cumulative coarse weights
};

__global__ __launch_bounds__(256) void nerf_k(
    const float* __restrict__ rays_o, const float* __restrict__ rays_d,
    const float* __restrict__ aabb,
    const float* __restrict__ sc,   // sigmas_coarse [N,128]
    const float* __restrict__ sfn,  // sigmas_fine   [N,64]
    const float* __restrict__ colors, // [N,64,16]
    const float* __restrict__ wv,   // [16,3]
    const float* __restrict__ bv,   // [3]
    float* __restrict__ out)
{
    __shared__ WarpSh sh[8];
    __shared__ float red[8][3];
    const int wid  = threadIdx.x >> 5;
    const int lane = threadIdx.x & 31;
    const int ray  = blockIdx.x * 8 + wid;
    WarpSh& W = sh[wid];

    // ---- near / far ----
    float o3[3], d3[3];
#pragma unroll
    for (int a = 0; a < 3; a++) { o3[a] = rays_o[ray * 3 + a]; d3[a] = rays_d[ray * 3 + a]; }
    float near = -1e30f, far = 1e30f;
#pragma unroll
    for (int a = 0; a < 3; a++) {
        float den = d3[a] + 1e-15f;
        float ta = (aabb[a] - o3[a]) / den;
        float tb = (aabb[a + 3] - o3[a]) / den;
        near = fmaxf(near, fminf(ta, tb));
        far  = fminf(far,  fmaxf(ta, tb));
    }
    bool bad = far < near;
    near = fmaxf(bad ? 1e9f : near, 0.05f);
    far  = bad ? 1e9f : far;
    const float s_near = spacing_fn(near), s_far = spacing_fn(far);

    // ---- coarse level: real bins + weights0 (lane owns i = 4*lane .. 4*lane+3) ----
    float rb[5];
#pragma unroll
    for (int k = 0; k < 5; k++) {
        float b = (float)(4 * lane + k) * (1.f / 128.f);
        float s = s_near * (1.f - b) + s_far * b;
        rb[k] = spacing_inv(s);
    }
    float4 sg4 = *(const float4*)(sc + (size_t)ray * NT0 + 4 * lane);
    float sig[4] = { sg4.x, sg4.y, sg4.z, sg4.w };
    float ds[4], pref[4];
    float lsum = 0.f;
#pragma unroll
    for (int k = 0; k < 4; k++) { ds[k] = (rb[k + 1] - rb[k]) * sig[k]; lsum += ds[k]; pref[k] = lsum; }
    float off = warp_incl_scan(lsum, lane) - lsum;
    float w0[4];
#pragma unroll
    for (int k = 0; k < 4; k++) {
        float excl = off + (pref[k] - ds[k]);
        w0[k] = n2n((1.f - expf(-ds[k])) * expf(-excl));
    }

    // cumulative coarse weights cw0 (129 entries)
    {
        float lw = 0.f, pw[4];
#pragma unroll
        for (int k = 0; k < 4; k++) { lw += w0[k]; pw[k] = lw; }
        float offw = warp_incl_scan(lw, lane) - lw;
        if (lane == 0) W.cw0[0] = 0.f;
#pragma unroll
        for (int k = 0; k < 4; k++) W.cw0[4 * lane + k + 1] = offw + pw[k];
    }

    // pdf -> cdf (129 entries, leading zero, clipped at 1)
    {
        float wq[4];
        float lq = 0.f;
#pragma unroll
        for (int k = 0; k < 4; k++) { wq[k] = w0[k] + 0.01f; lq += wq[k]; }
        float S = warp_red(lq);
        float invS = 1.f / S;
        float lp = 0.f, pp[4];
#pragma unroll
        for (int k = 0; k < 4; k++) { float p = wq[k] * invS; lp += p; pp[k] = lp; }
        float offp = warp_incl_scan(lp, lane) - lp;
        if (lane == 0) W.cdf[0] = 0.f;
#pragma unroll
        for (int k = 0; k < 4; k++) W.cdf[4 * lane + k + 1] = fminf(offp + pp[k], 1.f);
    }
    __syncwarp();

    // ---- sample_pdf: 65 fine bin edges ----
    {
        const float ustart = 0.5f / 65.f;
        const float ustop  = 1.f - 0.5f / 65.f;
        const float du = (ustop - ustart) / 64.f;
        for (int j = lane; j < 65; j += 32) {
            float u = ustart + (float)j * du;
            int lo = 0, hi = 129;
            while (lo < hi) { int m = (lo + hi) >> 1; if (W.cdf[m] <= u) lo = m + 1; else hi = m; }
            int below = lo - 1; if (below < 0) below = 0; if (below > 128) below = 128;
            int above = lo;     if (above > 128) above = 128;
            float c0 = W.cdf[below], c1 = W.cdf[above];
            float b0 = (float)below * (1.f / 128.f), b1 = (float)above * (1.f / 128.f);
            float t = n2n((u - c0) / (c1 - c0));
            t = fminf(fmaxf(t, 0.f), 1.f);
            float bb = b0 + t * (b1 - b0);
            W.bins1[j] = bb;
            float s = s_near * (1.f - bb) + s_far * bb;
            W.rb1[j] = spacing_inv(s);
        }
    }
    __syncwarp();

    // ---- fine level: lane owns i = 2*lane, 2*lane+1 ----
    const int i0 = 2 * lane;
    float rA = W.rb1[i0], rB = W.rb1[i0 + 1], rC = W.rb1[i0 + 2];
    float2 sf2 = *(const float2*)(sfn + (size_t)ray * NT1 + i0);
    float dsA = (rB - rA) * sf2.x;
    float dsB = (rC - rB) * sf2.y;
    {
        float l2 = dsA + dsB;
        float off2 = warp_incl_scan(l2, lane) - l2;
        float exA = off2, exB = off2 + dsA;
        dsA = n2n((1.f - expf(-dsA)) * expf(-exA));   // reuse regs: now weights
        dsB = n2n((1.f - expf(-dsB)) * expf(-exB));
    }
    const float wA = dsA, wB = dsB;
    const float tA = 0.5f * (rA + rB), tB = 0.5f * (rB + rC);

    // accumulations: weights_sum, depth, f_xyz, color partial matmul
    float wsum = wA + wB;
    float depth = wA * tA + wB * tB;
    float xA = o3[0] + d3[0] * tA, yA = o3[1] + d3[1] * tA, zA = o3[2] + d3[2] * tA;
    float xB = o3[0] + d3[0] * tB, yB = o3[1] + d3[1] * tB, zB = o3[2] + d3[2] * tB;
    contract_pt(xA, yA, zA);
    contract_pt(xB, yB, zB);
    float fx = wA * xA + wB * xB;
    float fy = wA * yA + wB * yB;
    float fz = wA * zA + wB * zB;

    float acc[NCH];
    {
        const float4* cp = (const float4*)(colors + ((size_t)ray * NT1 + i0) * NCH);
#pragma unroll
        for (int q = 0; q < 4; q++) {
            float4 v = cp[q];
            acc[4 * q + 0] = wA * v.x; acc[4 * q + 1] = wA * v.y;
            acc[4 * q + 2] = wA * v.z; acc[4 * q + 3] = wA * v.w;
        }
#pragma unroll
        for (int q = 0; q < 4; q++) {
            float4 v = cp[4 + q];
            acc[4 * q + 0] += wB * v.x; acc[4 * q + 1] += wB * v.y;
            acc[4 * q + 2] += wB * v.z; acc[4 * q + 3] += wB * v.w;
        }
    }
    float p0 = 0.f, p1 = 0.f, p2 = 0.f;
#pragma unroll
    for (int c = 0; c < NCH; c++) {
        float f = acc[c];
        p0 += f * wv[c * 3 + 0];
        p1 += f * wv[c * 3 + 1];
        p2 += f * wv[c * 3 + 2];
    }

    // ---- distortion loss pieces (bins space) ----
    float bA = W.bins1[i0], bB = W.bins1[i0 + 1], bC = W.bins1[i0 + 2];
    float iA = bB - bA, iB = bC - bB;
    float mA = bA + iA * 0.5f, mB = bB + iB * 0.5f;
    float uni = iA * wA * wA + iB * wB * wB;
    float wmA = wA * mA, wmB = wB * mB;
    float bi;
    {
        float lw = wA + wB;
        float offw = warp_incl_scan(lw, lane) - lw;
        float wexA = offw, wexB = offw + wA;
        float lm = wmA + wmB;
        float offm = warp_incl_scan(lm, lane) - lm;
        float mexA = offm, mexB = offm + wmA;
        bi = wmA * wexA - wA * mexA + wmB * wexB - wB * mexB;  // i=0 term is 0 automatically
    }

    // ---- interlevel (proposal) loss: closed-form searchsorted into uniform coarse grid ----
    float prop = 0.f;
#pragma unroll
    for (int k = 0; k < 2; k++) {
        int i = i0 + k;
        float w1v = (k == 0) ? wA : wB;
        float vlo = W.bins1[i], vhi = W.bins1[i + 1];
        // inds_lo = clip(searchsorted(bins0[:128], vlo, right) - 1, 0, 127)
        int c1 = (int)floorf(vlo * 128.f) + 1; if (c1 > 128) c1 = 128; if (c1 < 0) c1 = 0;
        int ilo = c1 - 1; if (ilo < 0) ilo = 0; if (ilo > 127) ilo = 127;
        // inds_hi = clip(searchsorted(bins0[1:129], vhi, right), 0, 127)
        int c2 = (int)floorf(vhi * 128.f); if (c2 > 128) c2 = 128; if (c2 < 0) c2 = 0;
        int ihi = c2; if (ihi > 127) ihi = 127;
        float w = W.cw0[ihi + 1] - W.cw0[ilo];
        float dlt = fmaxf(w1v - w, 0.f);
        prop += dlt * dlt / (w1v + 1e-8f);
    }

    // ---- reductions ----
    wsum  = warp_red(wsum);
    depth = warp_red(depth);
    fx = warp_red(fx); fy = warp_red(fy); fz = warp_red(fz);
    p0 = warp_red(p0); p1 = warp_red(p1); p2 = warp_red(p2);
    uni = warp_red(uni); bi = warp_red(bi); prop = warp_red(prop);

    if (lane == 0) {
        float bg = 1.f - wsum;
        float pk[3] = { p0, p1, p2 };
#pragma unroll
        for (int k = 0; k < 3; k++) {
            float v = pk[k] + bv[k];
            out[ray * 3 + k] = 1.f / (1.f + expf(-v)) + bg;
        }
        out[3 * NRAYS + ray] = depth;
        out[4 * NRAYS + ray * 3 + 0] = fx;
        out[4 * NRAYS + ray * 3 + 1] = fy;
        out[4 * NRAYS + ray * 3 + 2] = fz;
        red[wid][0] = prop; red[wid][1] = uni; red[wid][2] = bi;
    }
    __syncthreads();
    if (threadIdx.x < 3) {
        double s = 0.0;
#pragma unroll
        for (int w2 = 0; w2 < 8; w2++) s += (double)red[w2][threadIdx.x];
        atomicAdd(&g_acc[threadIdx.x], s);
    }
}

extern "C" void kernel_launch(void* const* d_in, const int* in_sizes, int n_in,
                              void* d_out, int out_size) {
    const float* rays_o = (const float*)d_in[0];
    const float* rays_d = (const float*)d_in[1];
    const float* aabb   = (const float*)d_in[2];
    const float* sc     = (const float*)d_in[3];
    const float* sfn    = (const float*)d_in[4];
    const float* colors = (const float*)d_in[5];
    const float* wv     = (const float*)d_in[6];
    const float* bv     = (const float*)d_in[7];
    float* out = (float*)d_out;

    init_k<<<1, 32>>>();
    nerf_k<<<NRAYS / 8, 256>>>(rays_o, rays_d, aabb, sc, sfn, colors, wv, bv, out);
    final_k<<<1, 1>>>(out);
}